// round 7
// baseline (speedup 1.0000x reference)
#include <cuda_runtime.h>
#include <cstdint>
#include <math.h>

// Problem constants
#define NSAMP 128
#define NDIM  24
#define SPAIRS 8128        // C(128,2)
#define FPAIRS 276         // C(24,2)
#define FS 2243328         // FPAIRS * SPAIRS
// jax pinv default rcond = 10 * max(M,N) * eps(f32) = 10*2*2^-23 = 2.384185791015625e-6 (exact f32)
#define RCOND 2.3841858e-6f
// slamch('E') for f32 = 2^-24
#define SEPS 5.9604645e-8f

__device__ __forceinline__ int row_start(int i, int n) {
    return (i * (2 * n - 1 - i)) >> 1;
}

// ---------------- LAPACK SLASV2 (netlib, verbatim, fp32) ----------------
// SVD of bidiagonal [[F, G], [0, H]]. Outputs signed ssmin/ssmax and rotations.
__device__ void slasv2_f32(float F, float G, float H,
                           float& ssmin, float& ssmax,
                           float& snr, float& csr, float& snl, float& csl)
{
    float FT = F, FA = fabsf(F), HT = H, HA = fabsf(H);
    int pmax = 1;
    bool swp = (HA > FA);
    if (swp) { pmax = 3; float t = FT; FT = HT; HT = t; t = FA; FA = HA; HA = t; }
    float GT = G, GA = fabsf(G);
    float clt = 0.f, crt = 0.f, slt = 0.f, srt = 0.f;
    if (GA == 0.0f) {
        ssmin = HA; ssmax = FA;
        clt = 1.0f; crt = 1.0f; slt = 0.0f; srt = 0.0f;
    } else {
        bool gasmal = true;
        if (GA > FA) {
            pmax = 2;
            if (__fdiv_rn(FA, GA) < SEPS) {
                gasmal = false;
                ssmax = GA;
                if (HA > 1.0f) ssmin = __fdiv_rn(FA, __fdiv_rn(GA, HA));
                else           ssmin = __fmul_rn(__fdiv_rn(FA, GA), HA);
                clt = 1.0f; slt = __fdiv_rn(HT, GT);
                srt = 1.0f; crt = __fdiv_rn(FT, GT);
            }
        }
        if (gasmal) {
            float D = __fsub_rn(FA, HA);
            float L = (D == FA) ? 1.0f : __fdiv_rn(D, FA);
            float M = __fdiv_rn(GT, FT);
            float T = __fsub_rn(2.0f, L);
            float MM = __fmul_rn(M, M);
            float TT = __fmul_rn(T, T);
            float S = sqrtf(__fadd_rn(TT, MM));          // TT, MM separate stmts: no fma
            float R = (L == 0.0f) ? fabsf(M) : sqrtf(fmaf(L, L, MM));  // L*L+MM contracts
            float A = __fmul_rn(0.5f, __fadd_rn(S, R));
            ssmin = __fdiv_rn(HA, A);
            ssmax = __fmul_rn(FA, A);
            if (MM == 0.0f) {
                if (L == 0.0f) T = __fmul_rn(copysignf(2.0f, FT), copysignf(1.0f, GT));
                else T = __fadd_rn(__fdiv_rn(GT, copysignf(D, FT)), __fdiv_rn(M, T));
            } else {
                T = __fmul_rn(__fadd_rn(__fdiv_rn(M, __fadd_rn(S, T)),
                                        __fdiv_rn(M, __fadd_rn(R, L))),
                              __fadd_rn(1.0f, A));
            }
            float L2 = sqrtf(fmaf(T, T, 4.0f));          // T*T+4 contracts
            crt = __fdiv_rn(2.0f, L2);
            srt = __fdiv_rn(T, L2);
            clt = __fdiv_rn(fmaf(srt, M, crt), A);       // (CRT + SRT*M)/A contracts
            slt = __fdiv_rn(__fmul_rn(__fdiv_rn(HT, FT), srt), A);
        }
    }
    if (swp) { csl = srt; snl = crt; csr = slt; snr = clt; }
    else     { csl = clt; snl = slt; csr = crt; snr = srt; }
    float tsign = 1.0f;
    if (pmax == 1) tsign = copysignf(1.0f, csr) * copysignf(1.0f, csl) * copysignf(1.0f, F);
    if (pmax == 2) tsign = copysignf(1.0f, snr) * copysignf(1.0f, csl) * copysignf(1.0f, G);
    if (pmax == 3) tsign = copysignf(1.0f, snr) * copysignf(1.0f, snl) * copysignf(1.0f, H);
    ssmax = copysignf(ssmax, tsign);
    ssmin = copysignf(ssmin, __fmul_rn(tsign, __fmul_rn(copysignf(1.0f, F), copysignf(1.0f, H))));
}

__global__ __launch_bounds__(256)
void robust_list_kernel(const int* __restrict__ labels,
                        const float* __restrict__ features,
                        float* __restrict__ out,
                        int write_indices)
{
    __shared__ float sp[NSAMP];   // lf[:, p]
    __shared__ float sq[NSAMP];   // lf[:, q]
    __shared__ float sb[NSAMP];   // y - 0.5

    const int f = blockIdx.y;
    int p = 0;
    while (row_start(p + 1, NDIM) <= f) p++;
    const int q = f - row_start(p, NDIM) + p + 1;

    const int t = threadIdx.x;
    if (t < NSAMP) {
        float y = 2.0f * (float)labels[t] - 1.0f;       // exact +-1
        sp[t] = y * features[t * NDIM + p];             // exact sign flip
        sq[t] = y * features[t * NDIM + q];
        sb[t] = y - 0.5f;                               // exact
    }
    __syncthreads();

    const int s = blockIdx.x * blockDim.x + t;
    if (s >= SPAIRS) return;

    float disc = (float)(65025 - 8 * s);
    int i = (int)floorf((255.0f - sqrtf(disc)) * 0.5f);
    if (i > 0 && row_start(i, NSAMP) > s) i--;
    if (row_start(i + 1, NSAMP) <= s) i++;
    const int j = s - row_start(i, NSAMP) + i + 1;

    // A = [[a11, a12], [a21, a22]] (row 1 = sample i), rhs = (b1v, b2v)
    const float a11 = sp[i], a12 = sq[i];
    const float a21 = sp[j], a22 = sq[j];
    const float b1v = sb[i], b2v = sb[j];

    // ---------- SGEBD2: one Householder (slarfg + slarf), fp32 ----------
    float d1, e, d2, v1, tau;
    if (a21 == 0.0f) {
        tau = 0.0f; v1 = 0.0f; d1 = a11; e = a12; d2 = a22;
    } else {
        // slapy2(a11, |a21|)
        float xa = fabsf(a11), ya = fabsf(a21);
        float w_ = fmaxf(xa, ya), z_ = fminf(xa, ya);
        float py;
        if (z_ == 0.0f) py = w_;
        else {
            float r = __fdiv_rn(z_, w_);
            py = __fmul_rn(w_, sqrtf(fmaf(r, r, 1.0f)));   // 1+(z/w)**2 contracts
        }
        float beta = -copysignf(py, a11);                  // -SIGN(py, alpha)
        tau = __fdiv_rn(__fsub_rn(beta, a11), beta);
        float rcp = __fdiv_rn(1.0f, __fsub_rn(a11, beta)); // sscal by 1/(alpha-beta)
        v1 = __fmul_rn(a21, rcp);
        d1 = beta;
        // slarf on column 2: sgemv('T') then sger(alpha=-tau)
        float wv   = fmaf(v1, a22, a12);                   // w = a12 + v1*a22
        float temp = __fmul_rn(-tau, wv);
        e  = __fadd_rn(a12, temp);
        d2 = fmaf(v1, temp, a22);
    }

    // ---------- SBDSQR n==2: slasv2 on [[d1, e], [0, d2]] ----------
    float ssmin, ssmax, snr, csr, snl, csl;
    slasv2_f32(d1, e, d2, ssmin, ssmax, snr, csr, snl, csl);

    // srot on identity: VT = [[csr, snr], [-snr, csr]], U_B = [[csl, -snl], [snl, csl]]
    float sigmx = ssmax, sigmn = ssmin;
    float vt00 = csr, vt01 = snr, vt10 = -snr, vt11 = csr;
    float u00 = csl, u01 = -snl, u10 = snl, u11 = csl;
    // make singular values positive (negate VT row)
    if (sigmx < 0.0f) { sigmx = -sigmx; vt00 = -vt00; vt01 = -vt01; }
    if (sigmn < 0.0f) { sigmn = -sigmn; vt10 = -vt10; vt11 = -vt11; }

    // ---------- SORM2R: U = H1 * U_B ----------
    if (tau != 0.0f) {
        float w0 = fmaf(v1, u10, u00), t0 = __fmul_rn(-tau, w0);
        u00 = __fadd_rn(u00, t0); u10 = fmaf(v1, t0, u10);
        float w1_ = fmaf(v1, u11, u01), t1 = __fmul_rn(-tau, w1_);
        u01 = __fadd_rn(u01, t1); u11 = fmaf(v1, t1, u11);
    }

    // ---------- jax pinv (fp32): cutoff, N = U^T / s, P = VT^T @ N ----------
    const float cutoff = __fmul_rn(RCOND, sigmx);
    const bool k1 = (sigmx > cutoff);
    const bool k2 = (sigmn > cutoff);
    const float N00 = k1 ? __fdiv_rn(u00, sigmx) : 0.0f;   // u(0,0)/s0
    const float N01 = k1 ? __fdiv_rn(u10, sigmx) : 0.0f;   // u(1,0)/s0
    const float N10 = k2 ? __fdiv_rn(u01, sigmn) : 0.0f;   // u(0,1)/s1
    const float N11 = k2 ? __fdiv_rn(u11, sigmn) : 0.0f;   // u(1,1)/s1
    // P(i,j) = vh(0,i)*N(0,j) + vh(1,i)*N(1,j)  (k-sum: mul then fma)
    const float P00 = fmaf(vt10, N10, __fmul_rn(vt00, N00));
    const float P01 = fmaf(vt10, N11, __fmul_rn(vt00, N01));
    const float P10 = fmaf(vt11, N10, __fmul_rn(vt01, N00));
    const float P11 = fmaf(vt11, N11, __fmul_rn(vt01, N01));

    // ---------- outer matmul (fp32): W = P @ b ----------
    const float w0 = fmaf(P01, b2v, __fmul_rn(P00, b1v));
    const float w1 = fmaf(P11, b2v, __fmul_rn(P10, b1v));

    const size_t idx = (size_t)f * SPAIRS + (size_t)s;
    float2* o2 = (float2*)out;
    o2[idx] = make_float2(w0, w1);
    if (write_indices) {
        o2[(size_t)FS + idx] = make_float2((float)p, (float)q);
    }
}

extern "C" void kernel_launch(void* const* d_in, const int* in_sizes, int n_in,
                              void* d_out, int out_size)
{
    const int*   labels   = (const int*)d_in[0];     // int32 [128]
    const float* features = (const float*)d_in[1];   // float32 [128,24]
    float* out = (float*)d_out;

    const int write_indices = (out_size >= 2 * FS * 2) ? 1 : 0;

    dim3 grid((SPAIRS + 255) / 256, FPAIRS, 1);
    robust_list_kernel<<<grid, 256>>>(labels, features, out, write_indices);
}

// round 8
// speedup vs baseline: 1.3238x; 1.3238x over previous
#include <cuda_runtime.h>
#include <cstdint>
#include <math.h>

// Problem constants
#define NSAMP 128
#define NDIM  24
#define SPAIRS 8128        // C(128,2)
#define FPAIRS 276         // C(24,2)
#define FS 2243328         // FPAIRS * SPAIRS
// jax pinv default rcond = 10 * max(M,N) * eps(f32)
#define RCOND 2.3841858e-6f
// slamch('E') for f32 = 2^-24
#define SEPS 5.9604645e-8f

__device__ __forceinline__ int row_start(int i, int n) {
    return (i * (2 * n - 1 - i)) >> 1;
}

// Fast (approx) division / sqrt for relative-accuracy-safe spots only.
__device__ __forceinline__ float fdivf(float a, float b) { return __fdividef(a, b); }
__device__ __forceinline__ float fsqrtf_a(float x) {
    float r; asm("sqrt.approx.f32 %0, %1;" : "=f"(r) : "f"(x)); return r;
}

// ---------------- LAPACK SLASV2 (netlib semantics; approx div/sqrt OK:
// relatively stable given fixed inputs) ----------------
__device__ void slasv2_f32(float F, float G, float H,
                           float& ssmin, float& ssmax,
                           float& snr, float& csr, float& snl, float& csl)
{
    float FT = F, FA = fabsf(F), HT = H, HA = fabsf(H);
    int pmax = 1;
    bool swp = (HA > FA);
    if (swp) { pmax = 3; float t = FT; FT = HT; HT = t; t = FA; FA = HA; HA = t; }
    float GT = G, GA = fabsf(G);
    float clt = 0.f, crt = 0.f, slt = 0.f, srt = 0.f;
    if (GA == 0.0f) {
        ssmin = HA; ssmax = FA;
        clt = 1.0f; crt = 1.0f; slt = 0.0f; srt = 0.0f;
    } else {
        bool gasmal = true;
        if (GA > FA) {
            pmax = 2;
            if (fdivf(FA, GA) < SEPS) {
                gasmal = false;
                ssmax = GA;
                if (HA > 1.0f) ssmin = fdivf(FA, fdivf(GA, HA));
                else           ssmin = __fmul_rn(fdivf(FA, GA), HA);
                clt = 1.0f; slt = fdivf(HT, GT);
                srt = 1.0f; crt = fdivf(FT, GT);
            }
        }
        if (gasmal) {
            float D = __fsub_rn(FA, HA);
            float L = (D == FA) ? 1.0f : fdivf(D, FA);
            float M = fdivf(GT, FT);
            float T = __fsub_rn(2.0f, L);
            float MM = __fmul_rn(M, M);
            float TT = __fmul_rn(T, T);
            float S = fsqrtf_a(__fadd_rn(TT, MM));
            float R = (L == 0.0f) ? fabsf(M) : fsqrtf_a(fmaf(L, L, MM));
            float A = __fmul_rn(0.5f, __fadd_rn(S, R));
            ssmin = fdivf(HA, A);
            ssmax = __fmul_rn(FA, A);
            if (MM == 0.0f) {
                if (L == 0.0f) T = __fmul_rn(copysignf(2.0f, FT), copysignf(1.0f, GT));
                else T = __fadd_rn(fdivf(GT, copysignf(D, FT)), fdivf(M, T));
            } else {
                T = __fmul_rn(__fadd_rn(fdivf(M, __fadd_rn(S, T)),
                                        fdivf(M, __fadd_rn(R, L))),
                              __fadd_rn(1.0f, A));
            }
            float L2 = fsqrtf_a(fmaf(T, T, 4.0f));
            crt = fdivf(2.0f, L2);
            srt = fdivf(T, L2);
            clt = fdivf(fmaf(srt, M, crt), A);
            slt = fdivf(__fmul_rn(fdivf(HT, FT), srt), A);
        }
    }
    if (swp) { csl = srt; snl = crt; csr = slt; snr = clt; }
    else     { csl = clt; snl = slt; csr = crt; snr = srt; }
    float tsign = 1.0f;
    if (pmax == 1) tsign = copysignf(1.0f, csr) * copysignf(1.0f, csl) * copysignf(1.0f, F);
    if (pmax == 2) tsign = copysignf(1.0f, snr) * copysignf(1.0f, csl) * copysignf(1.0f, G);
    if (pmax == 3) tsign = copysignf(1.0f, snr) * copysignf(1.0f, snl) * copysignf(1.0f, H);
    ssmax = copysignf(ssmax, tsign);
    ssmin = copysignf(ssmin, __fmul_rn(tsign, __fmul_rn(copysignf(1.0f, F), copysignf(1.0f, H))));
}

__global__ __launch_bounds__(256)
void robust_list_kernel(const int* __restrict__ labels,
                        const float* __restrict__ features,
                        float* __restrict__ out,
                        int write_indices)
{
    __shared__ float sp[NSAMP];   // lf[:, p]
    __shared__ float sq[NSAMP];   // lf[:, q]
    __shared__ float sb[NSAMP];   // y - 0.5

    const int f = blockIdx.y;
    // closed-form decode f -> (p, q): row_start(p,24) = p*(47-p)/2
    int p = (int)floorf((47.0f - fsqrtf_a((float)(2209 - 8 * f))) * 0.5f);
    if (p > 0 && row_start(p, NDIM) > f) p--;
    if (row_start(p + 1, NDIM) <= f) p++;
    const int q = f - row_start(p, NDIM) + p + 1;

    const int t = threadIdx.x;
    if (t < NSAMP) {
        float y = 2.0f * (float)labels[t] - 1.0f;       // exact +-1
        sp[t] = y * features[t * NDIM + p];             // exact sign flip
        sq[t] = y * features[t * NDIM + q];
        sb[t] = y - 0.5f;                               // exact
    }
    __syncthreads();

    const int s = blockIdx.x * blockDim.x + t;
    if (s >= SPAIRS) return;

    // decode s -> (i, j): approx sqrt fine, two-sided fixups absorb +-1
    int i = (int)floorf((255.0f - fsqrtf_a((float)(65025 - 8 * s))) * 0.5f);
    if (i > 0 && row_start(i, NSAMP) > s) i--;
    if (row_start(i + 1, NSAMP) <= s) i++;
    const int j = s - row_start(i, NSAMP) + i + 1;

    // A = [[a11, a12], [a21, a22]] (row 1 = sample i), rhs = (b1v, b2v)
    const float a11 = sp[i], a12 = sq[i];
    const float a21 = sp[j], a22 = sq[j];
    const float b1v = sb[i], b2v = sb[j];

    // ---------- SGEBD2 Householder: ERROR-CRITICAL, bit-faithful fp32 ----------
    float d1, e, d2, v1, tau;
    if (a21 == 0.0f) {
        tau = 0.0f; v1 = 0.0f; d1 = a11; e = a12; d2 = a22;
    } else {
        // slapy2(a11, |a21|) -- exact ops only
        float xa = fabsf(a11), ya = fabsf(a21);
        float w_ = fmaxf(xa, ya), z_ = fminf(xa, ya);
        float py;
        if (z_ == 0.0f) py = w_;
        else {
            float r = __fdiv_rn(z_, w_);
            py = __fmul_rn(w_, sqrtf(fmaf(r, r, 1.0f)));
        }
        float beta = -copysignf(py, a11);
        tau = __fdiv_rn(__fsub_rn(beta, a11), beta);
        float rcp = __fdiv_rn(1.0f, __fsub_rn(a11, beta));
        v1 = __fmul_rn(a21, rcp);
        d1 = beta;
        float wv   = fmaf(v1, a22, a12);
        float temp = __fmul_rn(-tau, wv);
        e  = __fadd_rn(a12, temp);
        d2 = fmaf(v1, temp, a22);
    }

    // ---------- SBDSQR n==2: slasv2 on [[d1, e], [0, d2]] ----------
    float ssmin, ssmax, snr, csr, snl, csl;
    slasv2_f32(d1, e, d2, ssmin, ssmax, snr, csr, snl, csl);

    float sigmx = ssmax, sigmn = ssmin;
    float vt00 = csr, vt01 = snr, vt10 = -snr, vt11 = csr;
    float u00 = csl, u01 = -snl, u10 = snl, u11 = csl;
    if (sigmx < 0.0f) { sigmx = -sigmx; vt00 = -vt00; vt01 = -vt01; }
    if (sigmn < 0.0f) { sigmn = -sigmn; vt10 = -vt10; vt11 = -vt11; }

    // ---------- SORM2R: U = H1 * U_B ----------
    if (tau != 0.0f) {
        float w0 = fmaf(v1, u10, u00), t0 = __fmul_rn(-tau, w0);
        u00 = __fadd_rn(u00, t0); u10 = fmaf(v1, t0, u10);
        float w1_ = fmaf(v1, u11, u01), t1 = __fmul_rn(-tau, w1_);
        u01 = __fadd_rn(u01, t1); u11 = fmaf(v1, t1, u11);
    }

    // ---------- jax pinv: cutoff, N = U^T / s (approx div: rel-ulp safe) ----------
    const float cutoff = __fmul_rn(RCOND, sigmx);
    const bool k1 = (sigmx > cutoff);
    const bool k2 = (sigmn > cutoff);
    const float N00 = k1 ? fdivf(u00, sigmx) : 0.0f;
    const float N01 = k1 ? fdivf(u10, sigmx) : 0.0f;
    const float N10 = k2 ? fdivf(u01, sigmn) : 0.0f;
    const float N11 = k2 ? fdivf(u11, sigmn) : 0.0f;
    const float P00 = fmaf(vt10, N10, __fmul_rn(vt00, N00));
    const float P01 = fmaf(vt10, N11, __fmul_rn(vt00, N01));
    const float P10 = fmaf(vt11, N10, __fmul_rn(vt01, N00));
    const float P11 = fmaf(vt11, N11, __fmul_rn(vt01, N01));

    // ---------- outer matmul (fp32): W = P @ b ----------
    const float w0 = fmaf(P01, b2v, __fmul_rn(P00, b1v));
    const float w1 = fmaf(P11, b2v, __fmul_rn(P10, b1v));

    const size_t idx = (size_t)f * SPAIRS + (size_t)s;
    float2* o2 = (float2*)out;
    o2[idx] = make_float2(w0, w1);
    if (write_indices) {
        o2[(size_t)FS + idx] = make_float2((float)p, (float)q);
    }
}

extern "C" void kernel_launch(void* const* d_in, const int* in_sizes, int n_in,
                              void* d_out, int out_size)
{
    const int*   labels   = (const int*)d_in[0];     // int32 [128]
    const float* features = (const float*)d_in[1];   // float32 [128,24]
    float* out = (float*)d_out;

    const int write_indices = (out_size >= 2 * FS * 2) ? 1 : 0;

    dim3 grid((SPAIRS + 255) / 256, FPAIRS, 1);
    robust_list_kernel<<<grid, 256>>>(labels, features, out, write_indices);
}

// round 9
// speedup vs baseline: 1.4978x; 1.1314x over previous
#include <cuda_runtime.h>
#include <cstdint>
#include <math.h>

// Problem constants
#define NSAMP 128
#define NDIM  24
#define NPAD  25           // shared row padding (conflict-free stride)
#define SPAIRS 8128        // C(128,2)
#define FPAIRS 276         // C(24,2)
#define FS 2243328         // FPAIRS * SPAIRS
// jax pinv default rcond = 10 * max(M,N) * eps(f32)
#define RCOND 2.3841858e-6f
// slamch('E') for f32 = 2^-24
#define SEPS 5.9604645e-8f

__device__ __forceinline__ int row_start(int i, int n) {
    return (i * (2 * n - 1 - i)) >> 1;
}

// Fast (approx) division / sqrt for relative-accuracy-safe spots only.
__device__ __forceinline__ float fdivf(float a, float b) { return __fdividef(a, b); }
__device__ __forceinline__ float fsqrtf_a(float x) {
    float r; asm("sqrt.approx.f32 %0, %1;" : "=f"(r) : "f"(x)); return r;
}

// ---------------- LAPACK SLASV2 (netlib semantics; approx div/sqrt:
// relatively stable given fixed bidiagonal inputs) ----------------
__device__ __forceinline__ void slasv2_f32(float F, float G, float H,
                           float& ssmin, float& ssmax,
                           float& snr, float& csr, float& snl, float& csl)
{
    float FT = F, FA = fabsf(F), HT = H, HA = fabsf(H);
    int pmax = 1;
    bool swp = (HA > FA);
    if (swp) { pmax = 3; float t = FT; FT = HT; HT = t; t = FA; FA = HA; HA = t; }
    float GT = G, GA = fabsf(G);
    float clt = 0.f, crt = 0.f, slt = 0.f, srt = 0.f;
    if (GA == 0.0f) {
        ssmin = HA; ssmax = FA;
        clt = 1.0f; crt = 1.0f; slt = 0.0f; srt = 0.0f;
    } else {
        bool gasmal = true;
        if (GA > FA) {
            pmax = 2;
            if (fdivf(FA, GA) < SEPS) {
                gasmal = false;
                ssmax = GA;
                if (HA > 1.0f) ssmin = fdivf(FA, fdivf(GA, HA));
                else           ssmin = __fmul_rn(fdivf(FA, GA), HA);
                clt = 1.0f; slt = fdivf(HT, GT);
                srt = 1.0f; crt = fdivf(FT, GT);
            }
        }
        if (gasmal) {
            float D = __fsub_rn(FA, HA);
            float L = (D == FA) ? 1.0f : fdivf(D, FA);
            float M = fdivf(GT, FT);
            float T = __fsub_rn(2.0f, L);
            float MM = __fmul_rn(M, M);
            float TT = __fmul_rn(T, T);
            float S = fsqrtf_a(__fadd_rn(TT, MM));
            float R = (L == 0.0f) ? fabsf(M) : fsqrtf_a(fmaf(L, L, MM));
            float A = __fmul_rn(0.5f, __fadd_rn(S, R));
            ssmin = fdivf(HA, A);
            ssmax = __fmul_rn(FA, A);
            if (MM == 0.0f) {
                if (L == 0.0f) T = __fmul_rn(copysignf(2.0f, FT), copysignf(1.0f, GT));
                else T = __fadd_rn(fdivf(GT, copysignf(D, FT)), fdivf(M, T));
            } else {
                T = __fmul_rn(__fadd_rn(fdivf(M, __fadd_rn(S, T)),
                                        fdivf(M, __fadd_rn(R, L))),
                              __fadd_rn(1.0f, A));
            }
            float L2 = fsqrtf_a(fmaf(T, T, 4.0f));
            crt = fdivf(2.0f, L2);
            srt = fdivf(T, L2);
            clt = fdivf(fmaf(srt, M, crt), A);
            slt = fdivf(__fmul_rn(fdivf(HT, FT), srt), A);
        }
    }
    if (swp) { csl = srt; snl = crt; csr = slt; snr = clt; }
    else     { csl = clt; snl = slt; csr = crt; snr = srt; }
    float tsign = 1.0f;
    if (pmax == 1) tsign = copysignf(1.0f, csr) * copysignf(1.0f, csl) * copysignf(1.0f, F);
    if (pmax == 2) tsign = copysignf(1.0f, snr) * copysignf(1.0f, csl) * copysignf(1.0f, G);
    if (pmax == 3) tsign = copysignf(1.0f, snr) * copysignf(1.0f, snl) * copysignf(1.0f, H);
    ssmax = copysignf(ssmax, tsign);
    ssmin = copysignf(ssmin, __fmul_rn(tsign, __fmul_rn(copysignf(1.0f, F), copysignf(1.0f, H))));
}

// grid = (ceil(SPAIRS/256), 23); thread = (s, p), loops q = p+1..23.
__global__ __launch_bounds__(256)
void robust_list_kernel(const int* __restrict__ labels,
                        const float* __restrict__ features,
                        float* __restrict__ out,
                        int write_indices)
{
    __shared__ float lf[NSAMP][NPAD];   // y * features, padded rows
    __shared__ float sb[NSAMP];         // y - 0.5

    const int t = threadIdx.x;
    // stage full lf (128x24) once per block; coalesced gmem reads
    for (int idx = t; idx < NSAMP * NDIM; idx += 256) {
        int r = idx / NDIM, c = idx - r * NDIM;
        float y = 2.0f * (float)labels[r] - 1.0f;       // exact +-1
        lf[r][c] = y * features[idx];                   // exact sign flip
    }
    if (t < NSAMP) sb[t] = (2.0f * (float)labels[t] - 1.0f) - 0.5f;  // exact
    __syncthreads();

    const int s = blockIdx.x * 256 + t;
    if (s >= SPAIRS) return;
    const int p = blockIdx.y;           // 0..22

    // decode s -> (i, j): approx sqrt + two-sided integer fixups
    int i = (int)floorf((255.0f - fsqrtf_a((float)(65025 - 8 * s))) * 0.5f);
    if (i > 0 && row_start(i, NSAMP) > s) i--;
    if (row_start(i + 1, NSAMP) <= s) i++;
    const int j = s - row_start(i, NSAMP) + i + 1;

    const float b1v = sb[i], b2v = sb[j];
    const float a11 = lf[i][p];
    const float a21 = lf[j][p];

    // ---------- SGEBD2 Householder (column 1 only -> (s,p)-invariant):
    // ERROR-CRITICAL, bit-faithful fp32; hoisted out of the q loop ----------
    float d1, v1, tau;
    if (a21 == 0.0f) {
        tau = 0.0f; v1 = 0.0f; d1 = a11;
    } else {
        float xa = fabsf(a11), ya = fabsf(a21);
        float w_ = fmaxf(xa, ya), z_ = fminf(xa, ya);
        float py;
        if (z_ == 0.0f) py = w_;
        else {
            float r = __fdiv_rn(z_, w_);
            py = __fmul_rn(w_, sqrtf(fmaf(r, r, 1.0f)));
        }
        float beta = -copysignf(py, a11);
        tau = __fdiv_rn(__fsub_rn(beta, a11), beta);
        float rcp = __fdiv_rn(1.0f, __fsub_rn(a11, beta));
        v1 = __fmul_rn(a21, rcp);
        d1 = beta;
    }
    const float ntau = -tau;

    float2* o2 = (float2*)out;
    size_t idx = (size_t)row_start(p, NDIM) * SPAIRS + (size_t)s;

    #pragma unroll 1
    for (int q = p + 1; q < NDIM; q++, idx += SPAIRS) {
        const float a12 = lf[i][q];     // broadcast within warp (same i)
        const float a22 = lf[j][q];     // stride-25: conflict-free

        // slarf on column 2 (tau==0 path is numerically identical through here)
        float e, d2;
        {
            float wv   = fmaf(v1, a22, a12);
            float temp = __fmul_rn(ntau, wv);
            e  = __fadd_rn(a12, temp);
            d2 = fmaf(v1, temp, a22);
        }

        // ---------- SBDSQR n==2: slasv2 on [[d1, e], [0, d2]] ----------
        float ssmin, ssmax, snr, csr, snl, csl;
        slasv2_f32(d1, e, d2, ssmin, ssmax, snr, csr, snl, csl);

        float sigmx = ssmax, sigmn = ssmin;
        float vt00 = csr, vt01 = snr, vt10 = -snr, vt11 = csr;
        float u00 = csl, u01 = -snl, u10 = snl, u11 = csl;
        if (sigmx < 0.0f) { sigmx = -sigmx; vt00 = -vt00; vt01 = -vt01; }
        if (sigmn < 0.0f) { sigmn = -sigmn; vt10 = -vt10; vt11 = -vt11; }

        // ---------- SORM2R: U = H1 * U_B ----------
        if (tau != 0.0f) {
            float w0_ = fmaf(v1, u10, u00), t0 = __fmul_rn(ntau, w0_);
            u00 = __fadd_rn(u00, t0); u10 = fmaf(v1, t0, u10);
            float w1_ = fmaf(v1, u11, u01), t1 = __fmul_rn(ntau, w1_);
            u01 = __fadd_rn(u01, t1); u11 = fmaf(v1, t1, u11);
        }

        // ---------- jax pinv: cutoff, N = U^T / s, P = VT^T @ N ----------
        const float cutoff = __fmul_rn(RCOND, sigmx);
        const bool k1 = (sigmx > cutoff);
        const bool k2 = (sigmn > cutoff);
        const float N00 = k1 ? fdivf(u00, sigmx) : 0.0f;
        const float N01 = k1 ? fdivf(u10, sigmx) : 0.0f;
        const float N10 = k2 ? fdivf(u01, sigmn) : 0.0f;
        const float N11 = k2 ? fdivf(u11, sigmn) : 0.0f;
        const float P00 = fmaf(vt10, N10, __fmul_rn(vt00, N00));
        const float P01 = fmaf(vt10, N11, __fmul_rn(vt00, N01));
        const float P10 = fmaf(vt11, N10, __fmul_rn(vt01, N00));
        const float P11 = fmaf(vt11, N11, __fmul_rn(vt01, N01));

        // ---------- outer matmul (fp32): W = P @ b ----------
        const float w0 = fmaf(P01, b2v, __fmul_rn(P00, b1v));
        const float w1 = fmaf(P11, b2v, __fmul_rn(P10, b1v));

        o2[idx] = make_float2(w0, w1);
        if (write_indices) {
            o2[(size_t)FS + idx] = make_float2((float)p, (float)q);
        }
    }
}

extern "C" void kernel_launch(void* const* d_in, const int* in_sizes, int n_in,
                              void* d_out, int out_size)
{
    const int*   labels   = (const int*)d_in[0];     // int32 [128]
    const float* features = (const float*)d_in[1];   // float32 [128,24]
    float* out = (float*)d_out;

    const int write_indices = (out_size >= 2 * FS * 2) ? 1 : 0;

    dim3 grid((SPAIRS + 255) / 256, NDIM - 1, 1);    // 32 x 23
    robust_list_kernel<<<grid, 256>>>(labels, features, out, write_indices);
}

// round 10
// speedup vs baseline: 2.6321x; 1.7573x over previous
#include <cuda_runtime.h>
#include <cstdint>
#include <math.h>

#define NSAMP 128
#define NDIM  24
#define SPAIRS 8128        // C(128,2)
#define FPAIRS 276         // C(24,2)
#define FS 2243328         // FPAIRS * SPAIRS
#define RCOND 2.3841858e-6f   // jax pinv: 10*max(M,N)*eps(f32)
#define SEPS 5.9604645e-8f    // slamch('E')

// Scratch (allowed: __device__ globals). Transposed lf + b vector.
__device__ float g_lfT[NDIM * NSAMP];   // [q][sample]
__device__ float g_bv[NSAMP];           // y - 0.5

__device__ __forceinline__ int row_start(int i, int n) {
    return (i * (2 * n - 1 - i)) >> 1;
}
__device__ __forceinline__ float fdivf(float a, float b) { return __fdividef(a, b); }
__device__ __forceinline__ float fsqrtf_a(float x) {
    float r; asm("sqrt.approx.f32 %0, %1;" : "=f"(r) : "f"(x)); return r;
}

// ---------------- LAPACK SLASV2 (rare slow path; netlib semantics) ----------------
__device__ void slasv2_f32(float F, float G, float H,
                           float& ssmin, float& ssmax,
                           float& snr, float& csr, float& snl, float& csl)
{
    float FT = F, FA = fabsf(F), HT = H, HA = fabsf(H);
    int pmax = 1;
    bool swp = (HA > FA);
    if (swp) { pmax = 3; float t = FT; FT = HT; HT = t; t = FA; FA = HA; HA = t; }
    float GT = G, GA = fabsf(G);
    float clt = 0.f, crt = 0.f, slt = 0.f, srt = 0.f;
    if (GA == 0.0f) {
        ssmin = HA; ssmax = FA;
        clt = 1.0f; crt = 1.0f; slt = 0.0f; srt = 0.0f;
    } else {
        bool gasmal = true;
        if (GA > FA) {
            pmax = 2;
            if (fdivf(FA, GA) < SEPS) {
                gasmal = false;
                ssmax = GA;
                if (HA > 1.0f) ssmin = fdivf(FA, fdivf(GA, HA));
                else           ssmin = __fmul_rn(fdivf(FA, GA), HA);
                clt = 1.0f; slt = fdivf(HT, GT);
                srt = 1.0f; crt = fdivf(FT, GT);
            }
        }
        if (gasmal) {
            float D = __fsub_rn(FA, HA);
            float L = (D == FA) ? 1.0f : fdivf(D, FA);
            float M = fdivf(GT, FT);
            float T = __fsub_rn(2.0f, L);
            float MM = __fmul_rn(M, M);
            float TT = __fmul_rn(T, T);
            float S = fsqrtf_a(__fadd_rn(TT, MM));
            float R = (L == 0.0f) ? fabsf(M) : fsqrtf_a(fmaf(L, L, MM));
            float A = __fmul_rn(0.5f, __fadd_rn(S, R));
            ssmin = fdivf(HA, A);
            ssmax = __fmul_rn(FA, A);
            if (MM == 0.0f) {
                if (L == 0.0f) T = __fmul_rn(copysignf(2.0f, FT), copysignf(1.0f, GT));
                else T = __fadd_rn(fdivf(GT, copysignf(D, FT)), fdivf(M, T));
            } else {
                T = __fmul_rn(__fadd_rn(fdivf(M, __fadd_rn(S, T)),
                                        fdivf(M, __fadd_rn(R, L))),
                              __fadd_rn(1.0f, A));
            }
            float L2 = fsqrtf_a(fmaf(T, T, 4.0f));
            crt = fdivf(2.0f, L2);
            srt = fdivf(T, L2);
            clt = fdivf(fmaf(srt, M, crt), A);
            slt = fdivf(__fmul_rn(fdivf(HT, FT), srt), A);
        }
    }
    if (swp) { csl = srt; snl = crt; csr = slt; snr = clt; }
    else     { csl = clt; snl = slt; csr = crt; snr = srt; }
    float tsign = 1.0f;
    if (pmax == 1) tsign = copysignf(1.0f, csr) * copysignf(1.0f, csl) * copysignf(1.0f, F);
    if (pmax == 2) tsign = copysignf(1.0f, snr) * copysignf(1.0f, csl) * copysignf(1.0f, G);
    if (pmax == 3) tsign = copysignf(1.0f, snr) * copysignf(1.0f, snl) * copysignf(1.0f, H);
    ssmax = copysignf(ssmax, tsign);
    ssmin = copysignf(ssmin, __fmul_rn(tsign, __fmul_rn(copysignf(1.0f, F), copysignf(1.0f, H))));
}

// Init: build transposed signed-feature matrix + b vector (tiny, one block).
__global__ void init_scratch(const int* __restrict__ labels,
                             const float* __restrict__ features)
{
    int r = threadIdx.x;
    if (r < NSAMP) {
        float y = 2.0f * (float)labels[r] - 1.0f;       // exact +-1
        g_bv[r] = y - 0.5f;                             // exact
        #pragma unroll
        for (int c = 0; c < NDIM; c++)
            g_lfT[c * NSAMP + r] = y * features[r * NDIM + c];  // exact sign flip
    }
}

// thread = (s, p), loops q = p+1..23. p = blockIdx.x/32 (longest p first).
__global__ __launch_bounds__(256)
void robust_list_kernel(float* __restrict__ out, int write_indices)
{
    const int bx = blockIdx.x;
    const int p  = bx >> 5;                 // 0..22
    const int s  = (bx & 31) * 256 + threadIdx.x;
    if (s >= SPAIRS) return;

    // decode s -> (i, j)
    int i = (int)floorf((255.0f - fsqrtf_a((float)(65025 - 8 * s))) * 0.5f);
    if (i > 0 && row_start(i, NSAMP) > s) i--;
    if (row_start(i + 1, NSAMP) <= s) i++;
    const int j = s - row_start(i, NSAMP) + i + 1;

    const float b1v = g_bv[i], b2v = g_bv[j];
    const float a11 = g_lfT[p * NSAMP + i];   // warp broadcast
    const float a21 = g_lfT[p * NSAMP + j];   // coalesced

    // ---- SGEBD2 Householder (q-invariant): ERROR-CRITICAL, bit-faithful fp32 ----
    float d1, v1, tau;
    if (a21 == 0.0f) {
        tau = 0.0f; v1 = 0.0f; d1 = a11;
    } else {
        float xa = fabsf(a11), ya = fabsf(a21);
        float w_ = fmaxf(xa, ya), z_ = fminf(xa, ya);
        float py;
        if (z_ == 0.0f) py = w_;
        else {
            float r = __fdiv_rn(z_, w_);
            py = __fmul_rn(w_, sqrtf(fmaf(r, r, 1.0f)));
        }
        float beta = -copysignf(py, a11);
        tau = __fdiv_rn(__fsub_rn(beta, a11), beta);
        float rcp = __fdiv_rn(1.0f, __fsub_rn(a11, beta));
        v1 = __fmul_rn(a21, rcp);
        d1 = beta;
    }
    const float ntau = -tau;
    const float d1sq = __fmul_rn(d1, d1);

    // c = H1 * b, also q-invariant (fast path only)
    const float wvb = fmaf(v1, b2v, b1v);
    const float tb  = __fmul_rn(ntau, wvb);
    const float c1  = __fadd_rn(b1v, tb);
    const float c2  = fmaf(v1, tb, b2v);

    float2* o2 = (float2*)out;
    size_t idx = (size_t)row_start(p, NDIM) * SPAIRS + (size_t)s;
    float qf = (float)(p + 1);
    const float pf = (float)p;

    #pragma unroll 1
    for (int q = p + 1; q < NDIM; q++, idx += SPAIRS, qf += 1.0f) {
        const float a12 = g_lfT[q * NSAMP + i];   // broadcast
        const float a22 = g_lfT[q * NSAMP + j];   // coalesced

        // slarf on column 2 (bit-identical to LAPACK realization)
        const float wv   = fmaf(v1, a22, a12);
        const float temp = __fmul_rn(ntau, wv);
        const float e    = __fadd_rn(a12, temp);
        const float d2   = fmaf(v1, temp, a22);

        const float det  = __fmul_rn(d1, d2);
        const float fro2 = fmaf(d2, d2, fmaf(e, e, d1sq));

        float w0, w1;
        if (fabsf(det) > 2.0f * RCOND * fro2) {
            // FAST: both sigmas provably kept -> pinv(B) = B^-1, triangular solve.
            // Agrees with the slasv2 route to ~few eps*||w|| absolute.
            w1 = fdivf(c2, d2);
            w0 = fdivf(fmaf(-e, w1, c1), d1);
        } else {
            // SLOW (rare): full LAPACK slasv2 + jax pinv path (exact criterion).
            float ssmin, ssmax, snr, csr, snl, csl;
            slasv2_f32(d1, e, d2, ssmin, ssmax, snr, csr, snl, csl);
            float sigmx = ssmax, sigmn = ssmin;
            float vt00 = csr, vt01 = snr, vt10 = -snr, vt11 = csr;
            float u00 = csl, u01 = -snl, u10 = snl, u11 = csl;
            if (sigmx < 0.0f) { sigmx = -sigmx; vt00 = -vt00; vt01 = -vt01; }
            if (sigmn < 0.0f) { sigmn = -sigmn; vt10 = -vt10; vt11 = -vt11; }
            if (tau != 0.0f) {   // SORM2R: U = H1 * U_B
                float w0_ = fmaf(v1, u10, u00), t0 = __fmul_rn(ntau, w0_);
                u00 = __fadd_rn(u00, t0); u10 = fmaf(v1, t0, u10);
                float w1_ = fmaf(v1, u11, u01), t1 = __fmul_rn(ntau, w1_);
                u01 = __fadd_rn(u01, t1); u11 = fmaf(v1, t1, u11);
            }
            const float cutoff = __fmul_rn(RCOND, sigmx);
            const bool k1 = (sigmx > cutoff);
            const bool k2 = (sigmn > cutoff);
            const float N00 = k1 ? fdivf(u00, sigmx) : 0.0f;
            const float N01 = k1 ? fdivf(u10, sigmx) : 0.0f;
            const float N10 = k2 ? fdivf(u01, sigmn) : 0.0f;
            const float N11 = k2 ? fdivf(u11, sigmn) : 0.0f;
            const float P00 = fmaf(vt10, N10, __fmul_rn(vt00, N00));
            const float P01 = fmaf(vt10, N11, __fmul_rn(vt00, N01));
            const float P10 = fmaf(vt11, N10, __fmul_rn(vt01, N00));
            const float P11 = fmaf(vt11, N11, __fmul_rn(vt01, N01));
            w0 = fmaf(P01, b2v, __fmul_rn(P00, b1v));
            w1 = fmaf(P11, b2v, __fmul_rn(P10, b1v));
        }

        o2[idx] = make_float2(w0, w1);
        if (write_indices) {
            o2[(size_t)FS + idx] = make_float2(pf, qf);
        }
    }
}

extern "C" void kernel_launch(void* const* d_in, const int* in_sizes, int n_in,
                              void* d_out, int out_size)
{
    const int*   labels   = (const int*)d_in[0];     // int32 [128]
    const float* features = (const float*)d_in[1];   // float32 [128,24]
    float* out = (float*)d_out;

    const int write_indices = (out_size >= 2 * FS * 2) ? 1 : 0;

    init_scratch<<<1, 128>>>(labels, features);
    robust_list_kernel<<<32 * (NDIM - 1), 256>>>(out, write_indices);
}

// round 13
// speedup vs baseline: 2.6424x; 1.0039x over previous
#include <cuda_runtime.h>
#include <cstdint>
#include <math.h>

#define NSAMP 128
#define NDIM  24
#define SPAIRS 8128        // C(128,2)
#define FPAIRS 276         // C(24,2)
#define FS 2243328         // FPAIRS * SPAIRS
#define RCOND 2.3841858e-6f   // jax pinv: 10*max(M,N)*eps(f32)
#define SEPS 5.9604645e-8f    // slamch('E')

__device__ __forceinline__ int row_start(int i, int n) {
    return (i * (2 * n - 1 - i)) >> 1;
}
__device__ __forceinline__ float fdivf(float a, float b) { return __fdividef(a, b); }
__device__ __forceinline__ float fsqrtf_a(float x) {
    float r; asm("sqrt.approx.f32 %0, %1;" : "=f"(r) : "f"(x)); return r;
}

// ---------------- LAPACK SLASV2 (rare slow path; netlib semantics) ----------------
__device__ void slasv2_f32(float F, float G, float H,
                           float& ssmin, float& ssmax,
                           float& snr, float& csr, float& snl, float& csl)
{
    float FT = F, FA = fabsf(F), HT = H, HA = fabsf(H);
    int pmax = 1;
    bool swp = (HA > FA);
    if (swp) { pmax = 3; float t = FT; FT = HT; HT = t; t = FA; FA = HA; HA = t; }
    float GT = G, GA = fabsf(G);
    float clt = 0.f, crt = 0.f, slt = 0.f, srt = 0.f;
    if (GA == 0.0f) {
        ssmin = HA; ssmax = FA;
        clt = 1.0f; crt = 1.0f; slt = 0.0f; srt = 0.0f;
    } else {
        bool gasmal = true;
        if (GA > FA) {
            pmax = 2;
            if (fdivf(FA, GA) < SEPS) {
                gasmal = false;
                ssmax = GA;
                if (HA > 1.0f) ssmin = fdivf(FA, fdivf(GA, HA));
                else           ssmin = __fmul_rn(fdivf(FA, GA), HA);
                clt = 1.0f; slt = fdivf(HT, GT);
                srt = 1.0f; crt = fdivf(FT, GT);
            }
        }
        if (gasmal) {
            float D = __fsub_rn(FA, HA);
            float L = (D == FA) ? 1.0f : fdivf(D, FA);
            float M = fdivf(GT, FT);
            float T = __fsub_rn(2.0f, L);
            float MM = __fmul_rn(M, M);
            float TT = __fmul_rn(T, T);
            float S = fsqrtf_a(__fadd_rn(TT, MM));
            float R = (L == 0.0f) ? fabsf(M) : fsqrtf_a(fmaf(L, L, MM));
            float A = __fmul_rn(0.5f, __fadd_rn(S, R));
            ssmin = fdivf(HA, A);
            ssmax = __fmul_rn(FA, A);
            if (MM == 0.0f) {
                if (L == 0.0f) T = __fmul_rn(copysignf(2.0f, FT), copysignf(1.0f, GT));
                else T = __fadd_rn(fdivf(GT, copysignf(D, FT)), fdivf(M, T));
            } else {
                T = __fmul_rn(__fadd_rn(fdivf(M, __fadd_rn(S, T)),
                                        fdivf(M, __fadd_rn(R, L))),
                              __fadd_rn(1.0f, A));
            }
            float L2 = fsqrtf_a(fmaf(T, T, 4.0f));
            crt = fdivf(2.0f, L2);
            srt = fdivf(T, L2);
            clt = fdivf(fmaf(srt, M, crt), A);
            slt = fdivf(__fmul_rn(fdivf(HT, FT), srt), A);
        }
    }
    if (swp) { csl = srt; snl = crt; csr = slt; snr = clt; }
    else     { csl = clt; snl = slt; csr = crt; snr = srt; }
    float tsign = 1.0f;
    if (pmax == 1) tsign = copysignf(1.0f, csr) * copysignf(1.0f, csl) * copysignf(1.0f, F);
    if (pmax == 2) tsign = copysignf(1.0f, snr) * copysignf(1.0f, csl) * copysignf(1.0f, G);
    if (pmax == 3) tsign = copysignf(1.0f, snr) * copysignf(1.0f, snl) * copysignf(1.0f, H);
    ssmax = copysignf(ssmax, tsign);
    ssmin = copysignf(ssmin, __fmul_rn(tsign, __fmul_rn(copysignf(1.0f, F), copysignf(1.0f, H))));
}

// grid = 12 p-groups x 32 s-chunks. Group g<11 handles p=g (23-g trips) AND
// p=21-g (2+g trips) -> constant 25 trips/block. Group 11 handles p=22 (1 trip).
__global__ __launch_bounds__(256)
void robust_list_kernel(const int* __restrict__ labels,
                        const float* __restrict__ features,
                        float* __restrict__ out, int write_indices)
{
    __shared__ float slf[NDIM][NSAMP];   // column-major signed features, 12 KB
    __shared__ float ssb[NSAMP];         // y - 0.5

    const int t = threadIdx.x;
    // stage: 3072 floats, coalesced; exact ops (sign flip only)
    for (int idx = t; idx < NSAMP * NDIM; idx += 256) {
        int r = idx / NDIM, c = idx - r * NDIM;
        float y = 2.0f * (float)labels[r] - 1.0f;
        slf[c][r] = y * features[idx];
    }
    if (t < NSAMP) ssb[t] = (2.0f * (float)labels[t] - 1.0f) - 0.5f;
    __syncthreads();

    const int g = blockIdx.x >> 5;                 // 0..11
    const int s = (blockIdx.x & 31) * 256 + t;
    if (s >= SPAIRS) return;

    // decode s -> (i, j)
    int i = (int)floorf((255.0f - fsqrtf_a((float)(65025 - 8 * s))) * 0.5f);
    if (i > 0 && row_start(i, NSAMP) > s) i--;
    if (row_start(i + 1, NSAMP) <= s) i++;
    const int j = s - row_start(i, NSAMP) + i + 1;

    const float b1v = ssb[i], b2v = ssb[j];
    float2* o2 = (float2*)out;

    const int nphase = (g == 11) ? 1 : 2;
    #pragma unroll 1
    for (int phase = 0; phase < nphase; phase++) {
        const int p = (g == 11) ? 22 : (phase ? 21 - g : g);

        const float a11 = slf[p][i];   // broadcast within warp
        const float a21 = slf[p][j];   // consecutive lanes -> conflict-free

        // ---- SGEBD2 Householder (q-invariant): ERROR-CRITICAL, bit-faithful ----
        float d1, v1, tau;
        if (a21 == 0.0f) {
            tau = 0.0f; v1 = 0.0f; d1 = a11;
        } else {
            float xa = fabsf(a11), ya = fabsf(a21);
            float w_ = fmaxf(xa, ya), z_ = fminf(xa, ya);
            float py;
            if (z_ == 0.0f) py = w_;
            else {
                float r = __fdiv_rn(z_, w_);
                py = __fmul_rn(w_, sqrtf(fmaf(r, r, 1.0f)));
            }
            float beta = -copysignf(py, a11);
            tau = __fdiv_rn(__fsub_rn(beta, a11), beta);
            float rcp = __fdiv_rn(1.0f, __fsub_rn(a11, beta));
            v1 = __fmul_rn(a21, rcp);
            d1 = beta;
        }
        const float ntau = -tau;
        const float d1sq = __fmul_rn(d1, d1);

        // c = H1 * b (q-invariant, fast path)
        const float wvb = fmaf(v1, b2v, b1v);
        const float tb  = __fmul_rn(ntau, wvb);
        const float c1  = __fadd_rn(b1v, tb);
        const float c2  = fmaf(v1, tb, b2v);

        size_t idx = (size_t)row_start(p, NDIM) * SPAIRS + (size_t)s;
        float qf = (float)(p + 1);
        const float pf = (float)p;

        #pragma unroll 1
        for (int q = p + 1; q < NDIM; q++, idx += SPAIRS, qf += 1.0f) {
            const float a12 = slf[q][i];
            const float a22 = slf[q][j];

            // slarf on column 2 (bit-identical to LAPACK realization)
            const float wv   = fmaf(v1, a22, a12);
            const float temp = __fmul_rn(ntau, wv);
            const float e    = __fadd_rn(a12, temp);
            const float d2   = fmaf(v1, temp, a22);

            const float det  = __fmul_rn(d1, d2);
            const float fro2 = fmaf(d2, d2, fmaf(e, e, d1sq));

            float w0, w1;
            if (fabsf(det) > 2.0f * RCOND * fro2) {
                // FAST: both sigmas provably kept -> pinv(B)=B^-1 triangular solve
                w1 = fdivf(c2, d2);
                w0 = fdivf(fmaf(-e, w1, c1), d1);
            } else {
                // SLOW (rare): verbatim LAPACK slasv2 + jax pinv path
                float ssmin, ssmax, snr, csr, snl, csl;
                slasv2_f32(d1, e, d2, ssmin, ssmax, snr, csr, snl, csl);
                float sigmx = ssmax, sigmn = ssmin;
                float vt00 = csr, vt01 = snr, vt10 = -snr, vt11 = csr;
                float u00 = csl, u01 = -snl, u10 = snl, u11 = csl;
                if (sigmx < 0.0f) { sigmx = -sigmx; vt00 = -vt00; vt01 = -vt01; }
                if (sigmn < 0.0f) { sigmn = -sigmn; vt10 = -vt10; vt11 = -vt11; }
                if (tau != 0.0f) {
                    float w0_ = fmaf(v1, u10, u00), t0 = __fmul_rn(ntau, w0_);
                    u00 = __fadd_rn(u00, t0); u10 = fmaf(v1, t0, u10);
                    float w1_ = fmaf(v1, u11, u01), t1 = __fmul_rn(ntau, w1_);
                    u01 = __fadd_rn(u01, t1); u11 = fmaf(v1, t1, u11);
                }
                const float cutoff = __fmul_rn(RCOND, sigmx);
                const bool k1 = (sigmx > cutoff);
                const bool k2 = (sigmn > cutoff);
                const float N00 = k1 ? fdivf(u00, sigmx) : 0.0f;
                const float N01 = k1 ? fdivf(u10, sigmx) : 0.0f;
                const float N10 = k2 ? fdivf(u01, sigmn) : 0.0f;
                const float N11 = k2 ? fdivf(u11, sigmn) : 0.0f;
                const float P00 = fmaf(vt10, N10, __fmul_rn(vt00, N00));
                const float P01 = fmaf(vt10, N11, __fmul_rn(vt00, N01));
                const float P10 = fmaf(vt11, N10, __fmul_rn(vt01, N00));
                const float P11 = fmaf(vt11, N11, __fmul_rn(vt01, N01));
                w0 = fmaf(P01, b2v, __fmul_rn(P00, b1v));
                w1 = fmaf(P11, b2v, __fmul_rn(P10, b1v));
            }

            o2[idx] = make_float2(w0, w1);
            if (write_indices) {
                o2[(size_t)FS + idx] = make_float2(pf, qf);
            }
        }
    }
}

extern "C" void kernel_launch(void* const* d_in, const int* in_sizes, int n_in,
                              void* d_out, int out_size)
{
    const int*   labels   = (const int*)d_in[0];     // int32 [128]
    const float* features = (const float*)d_in[1];   // float32 [128,24]
    float* out = (float*)d_out;

    const int write_indices = (out_size >= 2 * FS * 2) ? 1 : 0;

    robust_list_kernel<<<12 * 32, 256>>>(labels, features, out, write_indices);
}

// round 14
// speedup vs baseline: 3.3210x; 1.2568x over previous
#include <cuda_runtime.h>
#include <cstdint>
#include <math.h>

#define NSAMP 128
#define NDIM  24
#define SPAIRS 8128        // C(128,2)
#define FPAIRS 276         // C(24,2)
#define FS 2243328         // FPAIRS * SPAIRS
#define RCOND 2.3841858e-6f   // jax pinv: 10*max(M,N)*eps(f32)
#define SEPS 5.9604645e-8f    // slamch('E')
#define MAXTRIP 8
#define NCHUNK 45

// chunk tables: p, first q, trip count (q-range split into chunks of <=8)
__constant__ unsigned char c_p[NCHUNK] = {
    0,0,0, 1,1,1, 2,2,2, 3,3,3, 4,4,4, 5,5,5, 6,6,6,
    7,7, 8,8, 9,9, 10,10, 11,11, 12,12, 13,13, 14,14,
    15, 16, 17, 18, 19, 20, 21, 22 };
__constant__ unsigned char c_q0[NCHUNK] = {
    1,9,17, 2,10,18, 3,11,19, 4,12,20, 5,13,21, 6,14,22, 7,15,23,
    8,16, 9,17, 10,18, 11,19, 12,20, 13,21, 14,22, 15,23,
    16, 17, 18, 19, 20, 21, 22, 23 };
__constant__ unsigned char c_n[NCHUNK] = {
    8,8,7, 8,8,6, 8,8,5, 8,8,4, 8,8,3, 8,8,2, 8,8,1,
    8,8, 8,7, 8,6, 8,5, 8,4, 8,3, 8,2, 8,1,
    8, 7, 6, 5, 4, 3, 2, 1 };

__device__ __forceinline__ int row_start(int i, int n) {
    return (i * (2 * n - 1 - i)) >> 1;
}
__device__ __forceinline__ float fdivf(float a, float b) { return __fdividef(a, b); }
__device__ __forceinline__ float fsqrtf_a(float x) {
    float r; asm("sqrt.approx.f32 %0, %1;" : "=f"(r) : "f"(x)); return r;
}

// ---------------- LAPACK SLASV2 (rare slow path; netlib semantics) ----------------
__device__ void slasv2_f32(float F, float G, float H,
                           float& ssmin, float& ssmax,
                           float& snr, float& csr, float& snl, float& csl)
{
    float FT = F, FA = fabsf(F), HT = H, HA = fabsf(H);
    int pmax = 1;
    bool swp = (HA > FA);
    if (swp) { pmax = 3; float t = FT; FT = HT; HT = t; t = FA; FA = HA; HA = t; }
    float GT = G, GA = fabsf(G);
    float clt = 0.f, crt = 0.f, slt = 0.f, srt = 0.f;
    if (GA == 0.0f) {
        ssmin = HA; ssmax = FA;
        clt = 1.0f; crt = 1.0f; slt = 0.0f; srt = 0.0f;
    } else {
        bool gasmal = true;
        if (GA > FA) {
            pmax = 2;
            if (fdivf(FA, GA) < SEPS) {
                gasmal = false;
                ssmax = GA;
                if (HA > 1.0f) ssmin = fdivf(FA, fdivf(GA, HA));
                else           ssmin = __fmul_rn(fdivf(FA, GA), HA);
                clt = 1.0f; slt = fdivf(HT, GT);
                srt = 1.0f; crt = fdivf(FT, GT);
            }
        }
        if (gasmal) {
            float D = __fsub_rn(FA, HA);
            float L = (D == FA) ? 1.0f : fdivf(D, FA);
            float M = fdivf(GT, FT);
            float T = __fsub_rn(2.0f, L);
            float MM = __fmul_rn(M, M);
            float TT = __fmul_rn(T, T);
            float S = fsqrtf_a(__fadd_rn(TT, MM));
            float R = (L == 0.0f) ? fabsf(M) : fsqrtf_a(fmaf(L, L, MM));
            float A = __fmul_rn(0.5f, __fadd_rn(S, R));
            ssmin = fdivf(HA, A);
            ssmax = __fmul_rn(FA, A);
            if (MM == 0.0f) {
                if (L == 0.0f) T = __fmul_rn(copysignf(2.0f, FT), copysignf(1.0f, GT));
                else T = __fadd_rn(fdivf(GT, copysignf(D, FT)), fdivf(M, T));
            } else {
                T = __fmul_rn(__fadd_rn(fdivf(M, __fadd_rn(S, T)),
                                        fdivf(M, __fadd_rn(R, L))),
                              __fadd_rn(1.0f, A));
            }
            float L2 = fsqrtf_a(fmaf(T, T, 4.0f));
            crt = fdivf(2.0f, L2);
            srt = fdivf(T, L2);
            clt = fdivf(fmaf(srt, M, crt), A);
            slt = fdivf(__fmul_rn(fdivf(HT, FT), srt), A);
        }
    }
    if (swp) { csl = srt; snl = crt; csr = slt; snr = clt; }
    else     { csl = clt; snl = slt; csr = crt; snr = srt; }
    float tsign = 1.0f;
    if (pmax == 1) tsign = copysignf(1.0f, csr) * copysignf(1.0f, csl) * copysignf(1.0f, F);
    if (pmax == 2) tsign = copysignf(1.0f, snr) * copysignf(1.0f, csl) * copysignf(1.0f, G);
    if (pmax == 3) tsign = copysignf(1.0f, snr) * copysignf(1.0f, snl) * copysignf(1.0f, H);
    ssmax = copysignf(ssmax, tsign);
    ssmin = copysignf(ssmin, __fmul_rn(tsign, __fmul_rn(copysignf(1.0f, F), copysignf(1.0f, H))));
}

// grid = NCHUNK q-chunks x 32 s-chunks = 1440 blocks, <=8 trips each.
__global__ __launch_bounds__(256)
void robust_list_kernel(const int* __restrict__ labels,
                        const float* __restrict__ features,
                        float* __restrict__ out, int write_indices)
{
    __shared__ float scol[MAXTRIP + 1][NSAMP];   // col 0 = p, cols 1..ntr = q0..q0+ntr-1
    __shared__ float ssb[NSAMP];                 // y - 0.5

    const int t  = threadIdx.x;
    const int c  = blockIdx.x >> 5;
    const int p  = c_p[c];
    const int q0 = c_q0[c];
    const int ntr = c_n[c];

    // stage only the needed columns (exact ops: sign flip by +-1)
    const int ncols = ntr + 1;
    for (int idx = t; idx < ncols * NSAMP; idx += 256) {
        int cl = idx >> 7, r = idx & 127;
        int cg = (cl == 0) ? p : (q0 + cl - 1);
        float y = 2.0f * (float)labels[r] - 1.0f;
        scol[cl][r] = y * features[r * NDIM + cg];
    }
    if (t < NSAMP) ssb[t] = (2.0f * (float)labels[t] - 1.0f) - 0.5f;
    __syncthreads();

    const int s = (blockIdx.x & 31) * 256 + t;
    if (s >= SPAIRS) return;

    // decode s -> (i, j)
    int i = (int)floorf((255.0f - fsqrtf_a((float)(65025 - 8 * s))) * 0.5f);
    if (i > 0 && row_start(i, NSAMP) > s) i--;
    if (row_start(i + 1, NSAMP) <= s) i++;
    const int j = s - row_start(i, NSAMP) + i + 1;

    const float b1v = ssb[i], b2v = ssb[j];
    const float a11 = scol[0][i];   // broadcast within warp
    const float a21 = scol[0][j];   // consecutive lanes -> conflict-free

    // ---- SGEBD2 Householder (q-invariant): ERROR-CRITICAL, bit-faithful ----
    float d1, v1, tau;
    if (a21 == 0.0f) {
        tau = 0.0f; v1 = 0.0f; d1 = a11;
    } else {
        float xa = fabsf(a11), ya = fabsf(a21);
        float w_ = fmaxf(xa, ya), z_ = fminf(xa, ya);
        float py;
        if (z_ == 0.0f) py = w_;
        else {
            float r = __fdiv_rn(z_, w_);
            py = __fmul_rn(w_, sqrtf(fmaf(r, r, 1.0f)));
        }
        float beta = -copysignf(py, a11);
        tau = __fdiv_rn(__fsub_rn(beta, a11), beta);
        float rcp = __fdiv_rn(1.0f, __fsub_rn(a11, beta));
        v1 = __fmul_rn(a21, rcp);
        d1 = beta;
    }
    const float ntau = -tau;
    const float d1sq = __fmul_rn(d1, d1);

    // c = H1 * b (q-invariant, fast path)
    const float wvb = fmaf(v1, b2v, b1v);
    const float tb  = __fmul_rn(ntau, wvb);
    const float c1  = __fadd_rn(b1v, tb);
    const float c2  = fmaf(v1, tb, b2v);

    float2* o2 = (float2*)out;
    size_t idx = (size_t)(row_start(p, NDIM) + (q0 - p - 1)) * SPAIRS + (size_t)s;
    float qf = (float)q0;
    const float pf = (float)p;

    #pragma unroll 1
    for (int k = 0; k < ntr; k++, idx += SPAIRS, qf += 1.0f) {
        const float a12 = scol[1 + k][i];
        const float a22 = scol[1 + k][j];

        // slarf on column 2 (bit-identical to LAPACK realization)
        const float wv   = fmaf(v1, a22, a12);
        const float temp = __fmul_rn(ntau, wv);
        const float e    = __fadd_rn(a12, temp);
        const float d2   = fmaf(v1, temp, a22);

        const float det  = __fmul_rn(d1, d2);
        const float fro2 = fmaf(d2, d2, fmaf(e, e, d1sq));

        float w0, w1;
        if (fabsf(det) > 2.0f * RCOND * fro2) {
            // FAST: both sigmas provably kept -> pinv(B)=B^-1 triangular solve
            w1 = fdivf(c2, d2);
            w0 = fdivf(fmaf(-e, w1, c1), d1);
        } else {
            // SLOW (rare): verbatim LAPACK slasv2 + jax pinv path
            float ssmin, ssmax, snr, csr, snl, csl;
            slasv2_f32(d1, e, d2, ssmin, ssmax, snr, csr, snl, csl);
            float sigmx = ssmax, sigmn = ssmin;
            float vt00 = csr, vt01 = snr, vt10 = -snr, vt11 = csr;
            float u00 = csl, u01 = -snl, u10 = snl, u11 = csl;
            if (sigmx < 0.0f) { sigmx = -sigmx; vt00 = -vt00; vt01 = -vt01; }
            if (sigmn < 0.0f) { sigmn = -sigmn; vt10 = -vt10; vt11 = -vt11; }
            if (tau != 0.0f) {
                float w0_ = fmaf(v1, u10, u00), t0 = __fmul_rn(ntau, w0_);
                u00 = __fadd_rn(u00, t0); u10 = fmaf(v1, t0, u10);
                float w1_ = fmaf(v1, u11, u01), t1 = __fmul_rn(ntau, w1_);
                u01 = __fadd_rn(u01, t1); u11 = fmaf(v1, t1, u11);
            }
            const float cutoff = __fmul_rn(RCOND, sigmx);
            const bool k1 = (sigmx > cutoff);
            const bool k2 = (sigmn > cutoff);
            const float N00 = k1 ? fdivf(u00, sigmx) : 0.0f;
            const float N01 = k1 ? fdivf(u10, sigmx) : 0.0f;
            const float N10 = k2 ? fdivf(u01, sigmn) : 0.0f;
            const float N11 = k2 ? fdivf(u11, sigmn) : 0.0f;
            const float P00 = fmaf(vt10, N10, __fmul_rn(vt00, N00));
            const float P01 = fmaf(vt10, N11, __fmul_rn(vt00, N01));
            const float P10 = fmaf(vt11, N10, __fmul_rn(vt01, N00));
            const float P11 = fmaf(vt11, N11, __fmul_rn(vt01, N01));
            w0 = fmaf(P01, b2v, __fmul_rn(P00, b1v));
            w1 = fmaf(P11, b2v, __fmul_rn(P10, b1v));
        }

        o2[idx] = make_float2(w0, w1);
        if (write_indices) {
            o2[(size_t)FS + idx] = make_float2(pf, qf);
        }
    }
}

extern "C" void kernel_launch(void* const* d_in, const int* in_sizes, int n_in,
                              void* d_out, int out_size)
{
    const int*   labels   = (const int*)d_in[0];     // int32 [128]
    const float* features = (const float*)d_in[1];   // float32 [128,24]
    float* out = (float*)d_out;

    const int write_indices = (out_size >= 2 * FS * 2) ? 1 : 0;

    robust_list_kernel<<<NCHUNK * 32, 256>>>(labels, features, out, write_indices);
}